// round 5
// baseline (speedup 1.0000x reference)
#include <cuda_runtime.h>

// EmbeddingLayer: 16 sparse gathers + 2 sequence poolings (sum, nonzero-mean) + dense concat.
//
// R5 = R4 (best: pooling blocks first, 25-idx register preload, launch_bounds(256,4))
//      + cache-policy control:
//   - sparse-table gathers use __ldcs (evict-first; single-use rows from a
//     410MB table must not evict the 51MB seq tables from the 126MB L2)
//   - output stores use __stcs (streaming; write-once)
//   - seq-table gathers keep default caching -> should become L2-resident.

#define VOCAB   100000
#define BATCH   4096
#define EMBED   64
#define SEQLEN  50
#define NSPARSE 16
#define NDENSE  13
#define ROW_OUT (NSPARSE * EMBED + 2 * EMBED + NDENSE)  // 1165

#define SEQ_ROWS_PER_BLOCK 4                          // 4 rows x 2 feats = 8 warps
#define SEQ_BLOCKS (BATCH / SEQ_ROWS_PER_BLOCK)       // 1024  (blockIdx 0..1023)
#define SPARSE_BLOCKS BATCH                           // 4096  (blockIdx 1024..5119)
#define THREADS 256
#define HALF_SEQ (SEQLEN / 2)                         // 25

__global__ __launch_bounds__(THREADS, 4)
void embedding_layer_kernel(const float4* __restrict__ sp_tab,   // [16*VOCAB*16] float4
                            const float4* __restrict__ seq_tab,  // [ 2*VOCAB*16] float4
                            const float*  __restrict__ dense,    // [BATCH*13]
                            const int*    __restrict__ sp_idx,   // [16*BATCH]
                            const int*    __restrict__ sq_idx,   // [2*BATCH*50]
                            float*        __restrict__ out)      // [BATCH*1165]
{
    const int tid = threadIdx.x;

    if (blockIdx.x < SEQ_BLOCKS) {
        // ---- seq pooling: one warp per (batch row, feature) ----
        const int warp = tid >> 5;                       // 0..7
        const int lane = tid & 31;
        const int b    = blockIdx.x * SEQ_ROWS_PER_BLOCK + (warp >> 1);
        const int feat = warp & 1;                       // 0: sum, 1: nonzero-mean
        const int q    = lane & 15;                      // float4 lane in embed dim
        const int half = lane >> 4;                      // 0 -> [0,25), 1 -> [25,50)

        const int* __restrict__ ip =
            sq_idx + ((size_t)feat * BATCH + b) * SEQLEN + half * HALF_SEQ;
        const float4* __restrict__ tab = seq_tab + (size_t)feat * VOCAB * 16;

        // preload all indices -> gather loop is pure independent LDG.128s
        int idxs[HALF_SEQ];
        #pragma unroll
        for (int s = 0; s < HALF_SEQ; s++) idxs[s] = __ldg(&ip[s]);

        float4 acc = make_float4(0.f, 0.f, 0.f, 0.f);
        float4 cnt = make_float4(0.f, 0.f, 0.f, 0.f);

        #pragma unroll
        for (int s = 0; s < HALF_SEQ; s++) {
            float4 v = __ldg(&tab[(size_t)idxs[s] * 16 + q]);   // default: cache in L2
            acc.x += v.x; acc.y += v.y; acc.z += v.z; acc.w += v.w;
            if (feat) {
                cnt.x += (v.x != 0.f) ? 1.f : 0.f;
                cnt.y += (v.y != 0.f) ? 1.f : 0.f;
                cnt.z += (v.z != 0.f) ? 1.f : 0.f;
                cnt.w += (v.w != 0.f) ? 1.f : 0.f;
            }
        }

        // merge the two seq-halves (lanes l and l^16 share q)
        acc.x += __shfl_xor_sync(0xFFFFFFFFu, acc.x, 16);
        acc.y += __shfl_xor_sync(0xFFFFFFFFu, acc.y, 16);
        acc.z += __shfl_xor_sync(0xFFFFFFFFu, acc.z, 16);
        acc.w += __shfl_xor_sync(0xFFFFFFFFu, acc.w, 16);
        if (feat) {
            cnt.x += __shfl_xor_sync(0xFFFFFFFFu, cnt.x, 16);
            cnt.y += __shfl_xor_sync(0xFFFFFFFFu, cnt.y, 16);
            cnt.z += __shfl_xor_sync(0xFFFFFFFFu, cnt.z, 16);
            cnt.w += __shfl_xor_sync(0xFFFFFFFFu, cnt.w, 16);
        }

        if (half == 0) {
            float* o = out + (size_t)b * ROW_OUT + (NSPARSE + feat) * EMBED + q * 4;
            if (feat == 0) {
                __stcs(&o[0], acc.x); __stcs(&o[1], acc.y);
                __stcs(&o[2], acc.z); __stcs(&o[3], acc.w);
            } else {
                __stcs(&o[0], acc.x / (cnt.x + 1e-16f));
                __stcs(&o[1], acc.y / (cnt.y + 1e-16f));
                __stcs(&o[2], acc.z / (cnt.z + 1e-16f));
                __stcs(&o[3], acc.w / (cnt.w + 1e-16f));
            }
        }
    } else {
        // ---- sparse copy + dense tail: one block per batch row ----
        const int b = blockIdx.x - SEQ_BLOCKS;
        const int f = tid >> 4;      // feature 0..15
        const int q = tid & 15;      // float4 lane 0..15

        float* __restrict__ orow = out + (size_t)b * ROW_OUT;

        int idx = __ldg(&sp_idx[f * BATCH + b]);
        // single-use random row from 410MB table: evict-first, don't pollute L2
        float4 v = __ldcs(&sp_tab[((size_t)f * VOCAB + idx) * 16 + q]);
        float* o = orow + f * EMBED + q * 4;
        __stcs(&o[0], v.x); __stcs(&o[1], v.y);
        __stcs(&o[2], v.z); __stcs(&o[3], v.w);

        if (tid < NDENSE)
            __stcs(&orow[(NSPARSE + 2) * EMBED + tid],
                   __ldg(&dense[(size_t)b * NDENSE + tid]));
    }
}

extern "C" void kernel_launch(void* const* d_in, const int* in_sizes, int n_in,
                              void* d_out, int out_size) {
    const float* sp_tab  = (const float*)d_in[0];
    const float* seq_tab = (const float*)d_in[1];
    const float* dense   = (const float*)d_in[2];
    const int*   sp_idx  = (const int*)d_in[3];
    const int*   sq_idx  = (const int*)d_in[4];
    float*       out     = (float*)d_out;

    dim3 grid(SEQ_BLOCKS + SPARSE_BLOCKS);  // 5120 blocks, pooling first
    dim3 block(THREADS);
    embedding_layer_kernel<<<grid, block>>>(
        (const float4*)sp_tab, (const float4*)seq_tab, dense, sp_idx, sq_idx, out);
}

// round 6
// speedup vs baseline: 1.0017x; 1.0017x over previous
#include <cuda_runtime.h>

// EmbeddingLayer: 16 sparse gathers + 2 sequence poolings (sum, nonzero-mean) + dense concat.
//
// R6 = R4 structure (pooling blocks first, one warp per (row,feature), halves
//      merged by shfl_xor(16)) with the index preload replaced by a
//      cooperative load + shuffle:
//        lane l holds ip[l] (and ip[32+l] for l<18)  -> 2 regs instead of 25.
//      Gather loop gets idx via __shfl_sync, freeing registers for in-flight
//      LDG.128s, and launch_bounds(256,5) raises occupancy 32 -> 40 warps/SM.

#define VOCAB   100000
#define BATCH   4096
#define EMBED   64
#define SEQLEN  50
#define NSPARSE 16
#define NDENSE  13
#define ROW_OUT (NSPARSE * EMBED + 2 * EMBED + NDENSE)  // 1165

#define SEQ_ROWS_PER_BLOCK 4                          // 4 rows x 2 feats = 8 warps
#define SEQ_BLOCKS (BATCH / SEQ_ROWS_PER_BLOCK)       // 1024  (blockIdx 0..1023)
#define SPARSE_BLOCKS BATCH                           // 4096
#define THREADS 256
#define HALF_SEQ (SEQLEN / 2)                         // 25

__global__ __launch_bounds__(THREADS, 5)
void embedding_layer_kernel(const float4* __restrict__ sp_tab,   // [16*VOCAB*16] float4
                            const float4* __restrict__ seq_tab,  // [ 2*VOCAB*16] float4
                            const float*  __restrict__ dense,    // [BATCH*13]
                            const int*    __restrict__ sp_idx,   // [16*BATCH]
                            const int*    __restrict__ sq_idx,   // [2*BATCH*50]
                            float*        __restrict__ out)      // [BATCH*1165]
{
    const int tid = threadIdx.x;

    if (blockIdx.x < SEQ_BLOCKS) {
        // ---- seq pooling: one warp per (batch row, feature) ----
        const int warp = tid >> 5;                       // 0..7
        const int lane = tid & 31;
        const int b    = blockIdx.x * SEQ_ROWS_PER_BLOCK + (warp >> 1);
        const int feat = warp & 1;                       // 0: sum, 1: nonzero-mean
        const int q    = lane & 15;                      // float4 lane in embed dim
        const int half = lane >> 4;                      // 0 -> s'=[0,25), 1 -> s'=[25,50)

        const int* __restrict__ ip =
            sq_idx + ((size_t)feat * BATCH + b) * SEQLEN;
        const float4* __restrict__ tab = seq_tab + (size_t)feat * VOCAB * 16;

        // cooperative index load: lane l holds ip[l]; lanes 0..17 also ip[32+l]
        int idx_a = __ldg(&ip[lane]);                        // covers s' = 0..31
        int idx_b = (lane < SEQLEN - 32) ? __ldg(&ip[32 + lane]) : 0;  // s' = 32..49

        float4 acc = make_float4(0.f, 0.f, 0.f, 0.f);
        float4 cnt = make_float4(0.f, 0.f, 0.f, 0.f);

        #pragma unroll
        for (int s = 0; s < HALF_SEQ; s++) {
            // per-lane seq position s' = half*25 + s
            int idx;
            if (s < 7) {
                // both halves' s' < 32 -> source is idx_a, per-lane src lane
                int sp = half ? (s + 25) : s;
                idx = __shfl_sync(0xFFFFFFFFu, idx_a, sp);
            } else {
                // half0: s' = s (<32, from idx_a); half1: s' = s+25 (>=32, from idx_b)
                int va = __shfl_sync(0xFFFFFFFFu, idx_a, s);
                int vb = __shfl_sync(0xFFFFFFFFu, idx_b, s - 7);  // 32+(s-7) = s+25
                idx = half ? vb : va;
            }
            float4 v = __ldg(&tab[(size_t)idx * 16 + q]);
            acc.x += v.x; acc.y += v.y; acc.z += v.z; acc.w += v.w;
            if (feat) {
                cnt.x += (v.x != 0.f) ? 1.f : 0.f;
                cnt.y += (v.y != 0.f) ? 1.f : 0.f;
                cnt.z += (v.z != 0.f) ? 1.f : 0.f;
                cnt.w += (v.w != 0.f) ? 1.f : 0.f;
            }
        }

        // merge the two seq-halves (lanes l and l^16 share q)
        acc.x += __shfl_xor_sync(0xFFFFFFFFu, acc.x, 16);
        acc.y += __shfl_xor_sync(0xFFFFFFFFu, acc.y, 16);
        acc.z += __shfl_xor_sync(0xFFFFFFFFu, acc.z, 16);
        acc.w += __shfl_xor_sync(0xFFFFFFFFu, acc.w, 16);
        if (feat) {
            cnt.x += __shfl_xor_sync(0xFFFFFFFFu, cnt.x, 16);
            cnt.y += __shfl_xor_sync(0xFFFFFFFFu, cnt.y, 16);
            cnt.z += __shfl_xor_sync(0xFFFFFFFFu, cnt.z, 16);
            cnt.w += __shfl_xor_sync(0xFFFFFFFFu, cnt.w, 16);
        }

        if (half == 0) {
            float* o = out + (size_t)b * ROW_OUT + (NSPARSE + feat) * EMBED + q * 4;
            if (feat == 0) {
                o[0] = acc.x; o[1] = acc.y; o[2] = acc.z; o[3] = acc.w;
            } else {
                o[0] = acc.x / (cnt.x + 1e-16f);
                o[1] = acc.y / (cnt.y + 1e-16f);
                o[2] = acc.z / (cnt.z + 1e-16f);
                o[3] = acc.w / (cnt.w + 1e-16f);
            }
        }
    } else {
        // ---- sparse copy + dense tail: one block per batch row ----
        const int b = blockIdx.x - SEQ_BLOCKS;
        const int f = tid >> 4;      // feature 0..15
        const int q = tid & 15;      // float4 lane 0..15

        float* __restrict__ orow = out + (size_t)b * ROW_OUT;

        int idx = __ldg(&sp_idx[f * BATCH + b]);
        float4 v = __ldg(&sp_tab[((size_t)f * VOCAB + idx) * 16 + q]);
        float* o = orow + f * EMBED + q * 4;
        o[0] = v.x; o[1] = v.y; o[2] = v.z; o[3] = v.w;

        if (tid < NDENSE)
            orow[(NSPARSE + 2) * EMBED + tid] = __ldg(&dense[(size_t)b * NDENSE + tid]);
    }
}

extern "C" void kernel_launch(void* const* d_in, const int* in_sizes, int n_in,
                              void* d_out, int out_size) {
    const float* sp_tab  = (const float*)d_in[0];
    const float* seq_tab = (const float*)d_in[1];
    const float* dense   = (const float*)d_in[2];
    const int*   sp_idx  = (const int*)d_in[3];
    const int*   sq_idx  = (const int*)d_in[4];
    float*       out     = (float*)d_out;

    dim3 grid(SEQ_BLOCKS + SPARSE_BLOCKS);  // 5120 blocks, pooling first
    dim3 block(THREADS);
    embedding_layer_kernel<<<grid, block>>>(
        (const float4*)sp_tab, (const float4*)seq_tab, dense, sp_idx, sq_idx, out);
}

// round 7
// speedup vs baseline: 1.0152x; 1.0135x over previous
#include <cuda_runtime.h>

// EmbeddingLayer: 16 sparse gathers + 2 sequence poolings (sum, nonzero-mean) + dense concat.
//
// R7 = R6 (shuffle-distributed indices, one warp per (row,feature) pooling,
//      launch_bounds(256,5)) + single-wave persistent grid:
//   grid = 740 blocks (148 SMs x 5 resident blocks), each block loops over
//   work items with stride 740. Items 0..1023: pooling for 4 batch rows.
//   Items 1024..5119: sparse copy + dense for 1 batch row. Eliminates the
//   ~6 wave transitions of the 5120-block grid.

#define VOCAB   100000
#define BATCH   4096
#define EMBED   64
#define SEQLEN  50
#define NSPARSE 16
#define NDENSE  13
#define ROW_OUT (NSPARSE * EMBED + 2 * EMBED + NDENSE)  // 1165

#define SEQ_ROWS_PER_ITEM 4
#define SEQ_ITEMS  (BATCH / SEQ_ROWS_PER_ITEM)   // 1024
#define N_ITEMS    (SEQ_ITEMS + BATCH)           // 5120
#define GRID_BLOCKS 740                          // 148 SMs x 5 blocks
#define THREADS 256
#define HALF_SEQ (SEQLEN / 2)                    // 25

__global__ __launch_bounds__(THREADS, 5)
void embedding_layer_kernel(const float4* __restrict__ sp_tab,   // [16*VOCAB*16] float4
                            const float4* __restrict__ seq_tab,  // [ 2*VOCAB*16] float4
                            const float*  __restrict__ dense,    // [BATCH*13]
                            const int*    __restrict__ sp_idx,   // [16*BATCH]
                            const int*    __restrict__ sq_idx,   // [2*BATCH*50]
                            float*        __restrict__ out)      // [BATCH*1165]
{
    const int tid = threadIdx.x;

    #pragma unroll 1
    for (int item = blockIdx.x; item < N_ITEMS; item += GRID_BLOCKS) {
        if (item < SEQ_ITEMS) {
            // ---- seq pooling: one warp per (batch row, feature) ----
            const int warp = tid >> 5;                       // 0..7
            const int lane = tid & 31;
            const int b    = item * SEQ_ROWS_PER_ITEM + (warp >> 1);
            const int feat = warp & 1;                       // 0: sum, 1: nonzero-mean
            const int q    = lane & 15;                      // float4 lane in embed dim
            const int half = lane >> 4;                      // 0 -> s'=[0,25), 1 -> s'=[25,50)

            const int* __restrict__ ip =
                sq_idx + ((size_t)feat * BATCH + b) * SEQLEN;
            const float4* __restrict__ tab = seq_tab + (size_t)feat * VOCAB * 16;

            // cooperative index load: lane l holds ip[l]; lanes 0..17 also ip[32+l]
            int idx_a = __ldg(&ip[lane]);
            int idx_b = (lane < SEQLEN - 32) ? __ldg(&ip[32 + lane]) : 0;

            float4 acc = make_float4(0.f, 0.f, 0.f, 0.f);
            float4 cnt = make_float4(0.f, 0.f, 0.f, 0.f);

            #pragma unroll
            for (int s = 0; s < HALF_SEQ; s++) {
                int idx;
                if (s < 7) {
                    int sp = half ? (s + 25) : s;
                    idx = __shfl_sync(0xFFFFFFFFu, idx_a, sp);
                } else {
                    int va = __shfl_sync(0xFFFFFFFFu, idx_a, s);
                    int vb = __shfl_sync(0xFFFFFFFFu, idx_b, s - 7);  // 32+(s-7)=s+25
                    idx = half ? vb : va;
                }
                float4 v = __ldg(&tab[(size_t)idx * 16 + q]);
                acc.x += v.x; acc.y += v.y; acc.z += v.z; acc.w += v.w;
                if (feat) {
                    cnt.x += (v.x != 0.f) ? 1.f : 0.f;
                    cnt.y += (v.y != 0.f) ? 1.f : 0.f;
                    cnt.z += (v.z != 0.f) ? 1.f : 0.f;
                    cnt.w += (v.w != 0.f) ? 1.f : 0.f;
                }
            }

            // merge the two seq-halves (lanes l and l^16 share q)
            acc.x += __shfl_xor_sync(0xFFFFFFFFu, acc.x, 16);
            acc.y += __shfl_xor_sync(0xFFFFFFFFu, acc.y, 16);
            acc.z += __shfl_xor_sync(0xFFFFFFFFu, acc.z, 16);
            acc.w += __shfl_xor_sync(0xFFFFFFFFu, acc.w, 16);
            if (feat) {
                cnt.x += __shfl_xor_sync(0xFFFFFFFFu, cnt.x, 16);
                cnt.y += __shfl_xor_sync(0xFFFFFFFFu, cnt.y, 16);
                cnt.z += __shfl_xor_sync(0xFFFFFFFFu, cnt.z, 16);
                cnt.w += __shfl_xor_sync(0xFFFFFFFFu, cnt.w, 16);
            }

            if (half == 0) {
                float* o = out + (size_t)b * ROW_OUT + (NSPARSE + feat) * EMBED + q * 4;
                if (feat == 0) {
                    o[0] = acc.x; o[1] = acc.y; o[2] = acc.z; o[3] = acc.w;
                } else {
                    o[0] = acc.x / (cnt.x + 1e-16f);
                    o[1] = acc.y / (cnt.y + 1e-16f);
                    o[2] = acc.z / (cnt.z + 1e-16f);
                    o[3] = acc.w / (cnt.w + 1e-16f);
                }
            }
        } else {
            // ---- sparse copy + dense tail: one item per batch row ----
            const int b = item - SEQ_ITEMS;
            const int f = tid >> 4;      // feature 0..15
            const int q = tid & 15;      // float4 lane 0..15

            float* __restrict__ orow = out + (size_t)b * ROW_OUT;

            int idx = __ldg(&sp_idx[f * BATCH + b]);
            float4 v = __ldg(&sp_tab[((size_t)f * VOCAB + idx) * 16 + q]);
            float* o = orow + f * EMBED + q * 4;
            o[0] = v.x; o[1] = v.y; o[2] = v.z; o[3] = v.w;

            if (tid < NDENSE)
                orow[(NSPARSE + 2) * EMBED + tid] = __ldg(&dense[(size_t)b * NDENSE + tid]);
        }
    }
}

extern "C" void kernel_launch(void* const* d_in, const int* in_sizes, int n_in,
                              void* d_out, int out_size) {
    const float* sp_tab  = (const float*)d_in[0];
    const float* seq_tab = (const float*)d_in[1];
    const float* dense   = (const float*)d_in[2];
    const int*   sp_idx  = (const int*)d_in[3];
    const int*   sq_idx  = (const int*)d_in[4];
    float*       out     = (float*)d_out;

    embedding_layer_kernel<<<GRID_BLOCKS, THREADS>>>(
        (const float4*)sp_tab, (const float4*)seq_tab, dense, sp_idx, sq_idx, out);
}